// round 4
// baseline (speedup 1.0000x reference)
#include <cuda_runtime.h>
#include <cstdint>

#define NB   1024          // nb_code
#define CD   512           // C
#define AD   512           // attn_dim
#define TT   1024          // T
#define NT   65536         // N*T

// ---------------- scratch (device globals: allocation-free) ----------------
__device__ float  g_ku[NB * AD];              // unnormalized k
__device__ float  g_kdenom[NB];               // |k_j| + 1e-8 (fp32, from exact sumsq)
__device__ float  g_knT[AD * NB];             // normalized k, transposed [a][j]
__device__ float  g_q[(size_t)NT * AD];       // q; normalized in place by qnorm
__device__ float  g_logits[(size_t)NT * NB];  // logits, later overwritten with attn_w
__device__ float  g_avgp[32 * NB];            // avg_probs partial slots
__device__ int    g_counts[NB];
__device__ double g_ent;
__device__ double g_vq;

// ---------------- init ----------------
__global__ void init_kernel() {
    int i = blockIdx.x * 256 + threadIdx.x;
    if (i < NB) g_counts[i] = 0;
    if (i < 32 * NB) g_avgp[i] = 0.f;
    if (i == 0) { g_ent = 0.0; g_vq = 0.0; }
}

// ---------------- shared GEMM tile machinery ----------------
// Block: 256 threads, 64x64 output tile, BK=32, 4x4 microtile per thread.
// Accumulation is a single dependent fmaf chain per output, k strictly
// ascending -> matches cuBLAS/XLA serial-k fp32 semantics.

__device__ __forceinline__ void gemm_rowmajorA(
    const float* __restrict__ A, int lda,        // A row-major: elem (rr,kk) = A[rr*lda+kk]
    const float* __restrict__ B, int ldb,        // B k-major rows: elem (kk,cc) = B[kk*ldb+cc]
    int ksteps, float (&acc)[4][4])
{
    __shared__ __align__(16) float As[32][68];
    __shared__ __align__(16) float Bs[32][68];
    const int tid = threadIdx.x;
    const int aK = tid & 31, aR = tid >> 5;      // A loader: lanes along k (coalesced)
    const int bC = tid & 63, bK = tid >> 6;      // B loader: lanes along cols (coalesced)
    const int tx = tid & 15, ty = tid >> 4;
    for (int kt = 0; kt < ksteps; ++kt) {
#pragma unroll
        for (int p = 0; p < 8; ++p)
            As[aK][aR + p * 8] = A[(size_t)(aR + p * 8) * lda + aK];
#pragma unroll
        for (int p = 0; p < 8; ++p)
            Bs[bK + p * 4][bC] = B[(size_t)(bK + p * 4) * ldb + bC];
        __syncthreads();
#pragma unroll
        for (int kk = 0; kk < 32; ++kk) {
            float4 a4 = *(const float4*)&As[kk][ty * 4];
            float4 b4 = *(const float4*)&Bs[kk][tx * 4];
            float av[4] = {a4.x, a4.y, a4.z, a4.w};
            float bv[4] = {b4.x, b4.y, b4.z, b4.w};
#pragma unroll
            for (int i = 0; i < 4; ++i)
#pragma unroll
                for (int j = 0; j < 4; ++j)
                    acc[i][j] = fmaf(av[i], bv[j], acc[i][j]);
        }
        __syncthreads();
        A += 32;
        B += (size_t)32 * ldb;
    }
}

// A comes from x: elem (rr,kk) = A[kk*TT + rr] (k-major with stride T; rows=t contiguous)
__device__ __forceinline__ void gemm_xA(
    const float* __restrict__ A,
    const float* __restrict__ B, int ldb,
    int ksteps, float (&acc)[4][4])
{
    __shared__ __align__(16) float As[32][68];
    __shared__ __align__(16) float Bs[32][68];
    const int tid = threadIdx.x;
    const int aR = tid & 63, aK = tid >> 6;      // lanes along rows(t): coalesced in x
    const int bC = tid & 63, bK = tid >> 6;
    const int tx = tid & 15, ty = tid >> 4;
    for (int kt = 0; kt < ksteps; ++kt) {
#pragma unroll
        for (int p = 0; p < 8; ++p)
            As[aK + p * 4][aR] = A[(size_t)(aK + p * 4) * TT + aR];
#pragma unroll
        for (int p = 0; p < 8; ++p)
            Bs[bK + p * 4][bC] = B[(size_t)(bK + p * 4) * ldb + bC];
        __syncthreads();
#pragma unroll
        for (int kk = 0; kk < 32; ++kk) {
            float4 a4 = *(const float4*)&As[kk][ty * 4];
            float4 b4 = *(const float4*)&Bs[kk][tx * 4];
            float av[4] = {a4.x, a4.y, a4.z, a4.w};
            float bv[4] = {b4.x, b4.y, b4.z, b4.w};
#pragma unroll
            for (int i = 0; i < 4; ++i)
#pragma unroll
                for (int j = 0; j < 4; ++j)
                    acc[i][j] = fmaf(av[i], bv[j], acc[i][j]);
        }
        __syncthreads();
        A += (size_t)32 * TT;
        B += (size_t)32 * ldb;
    }
}

// ---------------- K1: ku = codebook @ Wk (unnormalized) ----------------
__global__ void __launch_bounds__(256) kproj_kernel(const float* __restrict__ cb,
                                                    const float* __restrict__ Wk)
{
    float acc[4][4] = {};
    const int j0 = blockIdx.y * 64, a0 = blockIdx.x * 64;
    gemm_rowmajorA(cb + (size_t)j0 * CD, CD, Wk + a0, AD, CD / 32, acc);
    const int tid = threadIdx.x, tx = tid & 15, ty = tid >> 4;
#pragma unroll
    for (int i = 0; i < 4; ++i) {
        int row = ty * 4 + i;
        float4 v = make_float4(acc[i][0], acc[i][1], acc[i][2], acc[i][3]);
        *(float4*)&g_ku[(size_t)(j0 + row) * AD + a0 + tx * 4] = v;
    }
}

// exact (double) sumsq per k row -> fp32 denom = sqrt + 1e-8
__global__ void __launch_bounds__(256) ksumsq_kernel() {
    const int warp = threadIdx.x >> 5, lane = threadIdx.x & 31;
    const int j = blockIdx.x * 8 + warp;          // grid 128 -> 1024 rows
    const float* k = g_ku + (size_t)j * AD;
    double s = 0.0;
#pragma unroll
    for (int i = 0; i < 16; ++i) { double t = (double)k[lane + i * 32]; s += t * t; }
#pragma unroll
    for (int o = 16; o; o >>= 1) s += __shfl_down_sync(0xffffffffu, s, o);
    if (lane == 0) g_kdenom[j] = __fsqrt_rn((float)s) + 1e-8f;
}

// normalize (IEEE fp32 divide) + transpose k -> g_knT[a][j]
__global__ void knorm_kernel() {
    int idx = blockIdx.x * 256 + threadIdx.x;   // 524288 total
    int j = idx >> 9, a = idx & 511;
    g_knT[(size_t)a * NB + j] = __fdiv_rn(g_ku[idx], g_kdenom[j]);
}

// ---------------- K2: q = xf @ Wq (unnormalized) ----------------
__global__ void __launch_bounds__(256) qproj_kernel(const float* __restrict__ x,
                                                    const float* __restrict__ Wq)
{
    float acc[4][4] = {};
    const int r0 = blockIdx.y * 64, a0 = blockIdx.x * 64;
    const int n = r0 >> 10, t0 = r0 & 1023;
    gemm_xA(x + (size_t)n * CD * TT + t0, Wq + a0, AD, CD / 32, acc);
    const int tid = threadIdx.x, tx = tid & 15, ty = tid >> 4;
#pragma unroll
    for (int i = 0; i < 4; ++i) {
        int row = ty * 4 + i;
        float4 v = make_float4(acc[i][0], acc[i][1], acc[i][2], acc[i][3]);
        *(float4*)&g_q[(size_t)(r0 + row) * AD + a0 + tx * 4] = v;
    }
}

// normalize q rows in place: exact sumsq (double), IEEE fp32 divide.
// Norm ulp wobble is a uniform row scale -> argmax invariant.
__global__ void __launch_bounds__(256) qnorm_kernel() {
    const int warp = threadIdx.x >> 5, lane = threadIdx.x & 31;
    const size_t r = (size_t)blockIdx.x * 8 + warp;   // grid 8192 -> 65536 rows
    float* q = g_q + r * AD;
    float v[16];
    double s = 0.0;
#pragma unroll
    for (int i = 0; i < 16; ++i) { v[i] = q[lane + i * 32]; s += (double)v[i] * v[i]; }
#pragma unroll
    for (int o = 16; o; o >>= 1) s += __shfl_down_sync(0xffffffffu, s, o);
    s = __shfl_sync(0xffffffffu, s, 0);
    float denom = __fsqrt_rn((float)s) + 1e-8f;
#pragma unroll
    for (int i = 0; i < 16; ++i) q[lane + i * 32] = __fdiv_rn(v[i], denom);
}

// ---------------- K3: logits = (qhat @ khatT) / f32(sqrt(512)) ----------------
__global__ void __launch_bounds__(256) logits_kernel()
{
    float acc[4][4] = {};
    const int r0 = blockIdx.y * 64, j0 = blockIdx.x * 64;
    gemm_rowmajorA(g_q + (size_t)r0 * AD, AD, g_knT + j0, NB, AD / 32, acc);
    const int tid = threadIdx.x, tx = tid & 15, ty = tid >> 4;
    const float SQ = 22.62741699796952f;        // f32(np.sqrt(512))
#pragma unroll
    for (int i = 0; i < 4; ++i) {
        int r = r0 + ty * 4 + i;
        float4 v = make_float4(__fdiv_rn(acc[i][0], SQ), __fdiv_rn(acc[i][1], SQ),
                               __fdiv_rn(acc[i][2], SQ), __fdiv_rn(acc[i][3], SQ));
        *(float4*)&g_logits[(size_t)r * NB + j0 + tx * 4] = v;
    }
}

// ---------------- K4: per-row argmax / softmax / entropy; overwrite logits with attn_w ----------------
__global__ void __launch_bounds__(256) rowpass_kernel(float* __restrict__ out)
{
    __shared__ float sl[8][1024];
    __shared__ float z1inv[8], z2inv[8], entp[8];
    const int tid = threadIdx.x;
    const size_t row0 = (size_t)blockIdx.x * 8;
    const float* src = g_logits + row0 * NB;
#pragma unroll
    for (int p = 0; p < 32; ++p)
        ((float*)sl)[p * 256 + tid] = src[p * 256 + tid];
    __syncthreads();

    const int warp = tid >> 5, lane = tid & 31;
    {
        float m = -1e30f; int mi = 0;
        float s1 = 0.f, s2 = 0.f, se = 0.f;
        for (int j = lane; j < 1024; j += 32) {
            float v = sl[warp][j];
            if (v > m) { m = v; mi = j; }
            s1 += expf(v);
            float l2 = v * 100.0f;        // logits / TEMP
            float e2 = expf(l2);
            s2 += e2;
            se = fmaf(e2, l2, se);
        }
#pragma unroll
        for (int o = 16; o; o >>= 1) {
            float mo = __shfl_down_sync(0xffffffffu, m, o);
            int mio = __shfl_down_sync(0xffffffffu, mi, o);
            if (mo > m || (mo == m && mio < mi)) { m = mo; mi = mio; }
            s1 += __shfl_down_sync(0xffffffffu, s1, o);
            s2 += __shfl_down_sync(0xffffffffu, s2, o);
            se += __shfl_down_sync(0xffffffffu, se, o);
        }
        if (lane == 0) {
            z1inv[warp] = 1.f / s1;
            z2inv[warp] = 1.f / s2;
            entp[warp] = se / s2 - logf(s2);          // sum_j p*log p for this row
            atomicAdd(&g_counts[mi], 1);
            out[33554437ULL + row0 + warp] = (float)mi;   // code_idx
        }
    }
    __syncthreads();
    if (tid == 0) {
        float e = 0.f;
#pragma unroll
        for (int w = 0; w < 8; ++w) e += entp[w];
        atomicAdd(&g_ent, (double)e);
    }
    // phase B: attn_w writeback + avg_probs partials
    float* attn = g_logits + row0 * NB;
#pragma unroll
    for (int k = 0; k < 4; ++k) {
        int j = tid + k * 256;
        float accp = 0.f;
#pragma unroll
        for (int r = 0; r < 8; ++r) {
            float v = sl[r][j];
            attn[(size_t)r * NB + j] = expf(v) * z1inv[r];
            accp = fmaf(expf(v * 100.0f), z2inv[r], accp);
        }
        atomicAdd(&g_avgp[(blockIdx.x & 31) * NB + j], accp);
    }
}

// ---------------- K5: z_q = attn @ codebook ; write x_d (==z_q) transposed + vq_loss ----------------
__global__ void __launch_bounds__(256) zq_kernel(const float* __restrict__ cb,
                                                 const float* __restrict__ x,
                                                 float* __restrict__ out)
{
    float acc[4][4] = {};
    const int r0 = blockIdx.y * 64, c0 = blockIdx.x * 64;
    const int n = r0 >> 10, t0 = r0 & 1023;
    gemm_rowmajorA(g_logits + (size_t)r0 * NB, NB, cb + c0, CD, NB / 32, acc);
    const int tid = threadIdx.x, tx = tid & 15, ty = tid >> 4;
    float vq = 0.f;
#pragma unroll
    for (int j = 0; j < 4; ++j) {
        int c = c0 + tx * 4 + j;
        size_t base = (size_t)n * CD * TT + (size_t)c * TT + t0 + ty * 4;
        float4 xv = *(const float4*)&x[base];
        float4 zv = make_float4(acc[0][j], acc[1][j], acc[2][j], acc[3][j]);
        *(float4*)&out[base] = zv;     // x_d = z_q (straight-through forward)
        float d0 = zv.x - xv.x, d1 = zv.y - xv.y, d2 = zv.z - xv.z, d3 = zv.w - xv.w;
        vq += d0 * d0 + d1 * d1 + d2 * d2 + d3 * d3;
    }
    __shared__ float red[256];
    red[tid] = vq;
    __syncthreads();
    for (int s = 128; s >= 1; s >>= 1) {
        if (tid < s) red[tid] += red[tid + s];
        __syncthreads();
    }
    if (tid == 0) atomicAdd(&g_vq, (double)red[0]);
}

// ---------------- K6: scalars ----------------
__global__ void finalize_kernel(float* __restrict__ out)
{
    const int j = threadIdx.x;  // 1024 threads
    double aps = 0.0;
#pragma unroll
    for (int s = 0; s < 32; ++s) aps += (double)g_avgp[s * NB + j];
    float ap = (float)(aps * (1.0 / 65536.0));
    float t1 = ap * logf(ap + 1e-5f);
    float pr = (float)g_counts[j] * (1.f / 65536.f);
    float t2 = pr * logf(pr + 1e-7f);

    __shared__ double r1[1024];
    __shared__ double r2[1024];
    r1[j] = (double)t1;
    r2[j] = (double)t2;
    __syncthreads();
    for (int s = 512; s >= 1; s >>= 1) {
        if (j < s) { r1[j] += r1[j + s]; r2[j] += r2[j + s]; }
        __syncthreads();
    }
    if (j == 0) {
        float avg_entropy = -(float)r1[0];
        float sample_entropy = -(float)(g_ent * (1.0 / 65536.0));
        out[33554432] = sample_entropy;
        out[33554433] = avg_entropy;
        out[33554434] = sample_entropy - avg_entropy;       // ent_loss
        out[33554435] = expf(-(float)r2[0]);                // perplexity
        out[33554436] = (float)(g_vq * (1.0 / 33554432.0)); // vq_loss
    }
}

// ---------------- launch ----------------
extern "C" void kernel_launch(void* const* d_in, const int* in_sizes, int n_in,
                              void* d_out, int out_size)
{
    const float* x  = (const float*)d_in[0];
    const float* cb = (const float*)d_in[1];
    const float* Wq = (const float*)d_in[2];
    const float* Wk = (const float*)d_in[3];
    float* out = (float*)d_out;

    init_kernel<<<256, 256>>>();
    kproj_kernel<<<dim3(8, 16), 256>>>(cb, Wk);
    ksumsq_kernel<<<128, 256>>>();
    knorm_kernel<<<2048, 256>>>();
    qproj_kernel<<<dim3(8, 1024), 256>>>(x, Wq);
    qnorm_kernel<<<8192, 256>>>();
    logits_kernel<<<dim3(16, 1024), 256>>>();
    rowpass_kernel<<<8192, 256>>>(out);
    zq_kernel<<<dim3(8, 1024), 256>>>(cb, x, out);
    finalize_kernel<<<1, 1024>>>(out);
}

// round 6
// speedup vs baseline: 1.0686x; 1.0686x over previous
#include <cuda_runtime.h>
#include <cuda_bf16.h>
#include <cstdint>

#define NB   1024          // nb_code
#define CD   512           // C
#define AD   512           // attn_dim
#define TT   1024          // T
#define NT   65536         // N*T

// ---------------- scratch (device globals: allocation-free) ----------------
__device__ float  g_ku[NB * AD];              // unnormalized k
__device__ float  g_kdenom[NB];               // |k_j| + 1e-8
__device__ float  g_knT[AD * NB];             // normalized k, transposed [a][j]
__device__ float  g_q[(size_t)NT * AD];       // q; normalized in place by qnorm
__device__ float  g_logits[(size_t)NT * NB];  // logits
__device__ __align__(16) __nv_bfloat16 g_attn_hi[(size_t)NT * NB];
__device__ __align__(16) __nv_bfloat16 g_attn_lo[(size_t)NT * NB];
__device__ __align__(16) __nv_bfloat16 g_cbT_hi[CD * NB];   // [c][j]
__device__ __align__(16) __nv_bfloat16 g_cbT_lo[CD * NB];
__device__ float  g_avgp[32 * NB];            // avg_probs partial slots
__device__ int    g_counts[NB];
__device__ double g_ent;
__device__ double g_vq;

// ---------------- init ----------------
__global__ void init_kernel() {
    int i = blockIdx.x * 256 + threadIdx.x;
    if (i < NB) g_counts[i] = 0;
    if (i < 32 * NB) g_avgp[i] = 0.f;
    if (i == 0) { g_ent = 0.0; g_vq = 0.0; }
}

// ---------------- SIMT GEMM tile machinery (exact path, unchanged) ----------------
__device__ __forceinline__ void gemm_rowmajorA(
    const float* __restrict__ A, int lda,
    const float* __restrict__ B, int ldb,
    int ksteps, float (&acc)[4][4])
{
    __shared__ __align__(16) float As[32][68];
    __shared__ __align__(16) float Bs[32][68];
    const int tid = threadIdx.x;
    const int aK = tid & 31, aR = tid >> 5;
    const int bC = tid & 63, bK = tid >> 6;
    const int tx = tid & 15, ty = tid >> 4;
    for (int kt = 0; kt < ksteps; ++kt) {
#pragma unroll
        for (int p = 0; p < 8; ++p)
            As[aK][aR + p * 8] = A[(size_t)(aR + p * 8) * lda + aK];
#pragma unroll
        for (int p = 0; p < 8; ++p)
            Bs[bK + p * 4][bC] = B[(size_t)(bK + p * 4) * ldb + bC];
        __syncthreads();
#pragma unroll
        for (int kk = 0; kk < 32; ++kk) {
            float4 a4 = *(const float4*)&As[kk][ty * 4];
            float4 b4 = *(const float4*)&Bs[kk][tx * 4];
            float av[4] = {a4.x, a4.y, a4.z, a4.w};
            float bv[4] = {b4.x, b4.y, b4.z, b4.w};
#pragma unroll
            for (int i = 0; i < 4; ++i)
#pragma unroll
                for (int j = 0; j < 4; ++j)
                    acc[i][j] = fmaf(av[i], bv[j], acc[i][j]);
        }
        __syncthreads();
        A += 32;
        B += (size_t)32 * ldb;
    }
}

__device__ __forceinline__ void gemm_xA(
    const float* __restrict__ A,
    const float* __restrict__ B, int ldb,
    int ksteps, float (&acc)[4][4])
{
    __shared__ __align__(16) float As[32][68];
    __shared__ __align__(16) float Bs[32][68];
    const int tid = threadIdx.x;
    const int aR = tid & 63, aK = tid >> 6;
    const int bC = tid & 63, bK = tid >> 6;
    const int tx = tid & 15, ty = tid >> 4;
    for (int kt = 0; kt < ksteps; ++kt) {
#pragma unroll
        for (int p = 0; p < 8; ++p)
            As[aK + p * 4][aR] = A[(size_t)(aK + p * 4) * TT + aR];
#pragma unroll
        for (int p = 0; p < 8; ++p)
            Bs[bK + p * 4][bC] = B[(size_t)(bK + p * 4) * ldb + bC];
        __syncthreads();
#pragma unroll
        for (int kk = 0; kk < 32; ++kk) {
            float4 a4 = *(const float4*)&As[kk][ty * 4];
            float4 b4 = *(const float4*)&Bs[kk][tx * 4];
            float av[4] = {a4.x, a4.y, a4.z, a4.w};
            float bv[4] = {b4.x, b4.y, b4.z, b4.w};
#pragma unroll
            for (int i = 0; i < 4; ++i)
#pragma unroll
                for (int j = 0; j < 4; ++j)
                    acc[i][j] = fmaf(av[i], bv[j], acc[i][j]);
        }
        __syncthreads();
        A += (size_t)32 * TT;
        B += (size_t)32 * ldb;
    }
}

// ---------------- K1: ku = codebook @ Wk ----------------
__global__ void __launch_bounds__(256) kproj_kernel(const float* __restrict__ cb,
                                                    const float* __restrict__ Wk)
{
    float acc[4][4] = {};
    const int j0 = blockIdx.y * 64, a0 = blockIdx.x * 64;
    gemm_rowmajorA(cb + (size_t)j0 * CD, CD, Wk + a0, AD, CD / 32, acc);
    const int tid = threadIdx.x, tx = tid & 15, ty = tid >> 4;
#pragma unroll
    for (int i = 0; i < 4; ++i) {
        int row = ty * 4 + i;
        float4 v = make_float4(acc[i][0], acc[i][1], acc[i][2], acc[i][3]);
        *(float4*)&g_ku[(size_t)(j0 + row) * AD + a0 + tx * 4] = v;
    }
}

__global__ void __launch_bounds__(256) ksumsq_kernel() {
    const int warp = threadIdx.x >> 5, lane = threadIdx.x & 31;
    const int j = blockIdx.x * 8 + warp;
    const float* k = g_ku + (size_t)j * AD;
    double s = 0.0;
#pragma unroll
    for (int i = 0; i < 16; ++i) { double t = (double)k[lane + i * 32]; s += t * t; }
#pragma unroll
    for (int o = 16; o; o >>= 1) s += __shfl_down_sync(0xffffffffu, s, o);
    if (lane == 0) g_kdenom[j] = __fsqrt_rn((float)s) + 1e-8f;
}

__global__ void knorm_kernel() {
    int idx = blockIdx.x * 256 + threadIdx.x;
    int j = idx >> 9, a = idx & 511;
    g_knT[(size_t)a * NB + j] = __fdiv_rn(g_ku[idx], g_kdenom[j]);
}

// ---------------- K2: q = xf @ Wq ----------------
__global__ void __launch_bounds__(256) qproj_kernel(const float* __restrict__ x,
                                                    const float* __restrict__ Wq)
{
    float acc[4][4] = {};
    const int r0 = blockIdx.y * 64, a0 = blockIdx.x * 64;
    const int n = r0 >> 10, t0 = r0 & 1023;
    gemm_xA(x + (size_t)n * CD * TT + t0, Wq + a0, AD, CD / 32, acc);
    const int tid = threadIdx.x, tx = tid & 15, ty = tid >> 4;
#pragma unroll
    for (int i = 0; i < 4; ++i) {
        int row = ty * 4 + i;
        float4 v = make_float4(acc[i][0], acc[i][1], acc[i][2], acc[i][3]);
        *(float4*)&g_q[(size_t)(r0 + row) * AD + a0 + tx * 4] = v;
    }
}

__global__ void __launch_bounds__(256) qnorm_kernel() {
    const int warp = threadIdx.x >> 5, lane = threadIdx.x & 31;
    const size_t r = (size_t)blockIdx.x * 8 + warp;
    float* q = g_q + r * AD;
    float v[16];
    double s = 0.0;
#pragma unroll
    for (int i = 0; i < 16; ++i) { v[i] = q[lane + i * 32]; s += (double)v[i] * v[i]; }
#pragma unroll
    for (int o = 16; o; o >>= 1) s += __shfl_down_sync(0xffffffffu, s, o);
    s = __shfl_sync(0xffffffffu, s, 0);
    float denom = __fsqrt_rn((float)s) + 1e-8f;
#pragma unroll
    for (int i = 0; i < 16; ++i) q[lane + i * 32] = __fdiv_rn(v[i], denom);
}

// ---------------- K3: logits ----------------
__global__ void __launch_bounds__(256) logits_kernel()
{
    float acc[4][4] = {};
    const int r0 = blockIdx.y * 64, j0 = blockIdx.x * 64;
    gemm_rowmajorA(g_q + (size_t)r0 * AD, AD, g_knT + j0, NB, AD / 32, acc);
    const int tid = threadIdx.x, tx = tid & 15, ty = tid >> 4;
    const float SQ = 22.62741699796952f;
#pragma unroll
    for (int i = 0; i < 4; ++i) {
        int r = r0 + ty * 4 + i;
        float4 v = make_float4(__fdiv_rn(acc[i][0], SQ), __fdiv_rn(acc[i][1], SQ),
                               __fdiv_rn(acc[i][2], SQ), __fdiv_rn(acc[i][3], SQ));
        *(float4*)&g_logits[(size_t)r * NB + j0 + tx * 4] = v;
    }
}

// ---------------- cbT split prep ----------------
__global__ void cbt_kernel(const float* __restrict__ cb) {
    int idx = blockIdx.x * 256 + threadIdx.x;   // 524288: idx = c*NB + j
    int c = idx >> 10, j = idx & 1023;
    float v = cb[(size_t)j * CD + c];
    __nv_bfloat16 h = __float2bfloat16(v);
    g_cbT_hi[idx] = h;
    g_cbT_lo[idx] = __float2bfloat16(v - __bfloat162float(h));
}

// ---------------- K4: row pass; emits attn as bf16 hi/lo splits ----------------
__global__ void __launch_bounds__(256) rowpass_kernel(float* __restrict__ out)
{
    __shared__ float sl[8][1024];
    __shared__ float z1inv[8], z2inv[8], entp[8];
    const int tid = threadIdx.x;
    const size_t row0 = (size_t)blockIdx.x * 8;
    const float* src = g_logits + row0 * NB;
#pragma unroll
    for (int p = 0; p < 32; ++p)
        ((float*)sl)[p * 256 + tid] = src[p * 256 + tid];
    __syncthreads();

    const int warp = tid >> 5, lane = tid & 31;
    {
        float m = -1e30f; int mi = 0;
        float s1 = 0.f, s2 = 0.f, se = 0.f;
        for (int j = lane; j < 1024; j += 32) {
            float v = sl[warp][j];
            if (v > m) { m = v; mi = j; }
            s1 += expf(v);
            float l2 = v * 100.0f;
            float e2 = expf(l2);
            s2 += e2;
            se = fmaf(e2, l2, se);
        }
#pragma unroll
        for (int o = 16; o; o >>= 1) {
            float mo = __shfl_down_sync(0xffffffffu, m, o);
            int mio = __shfl_down_sync(0xffffffffu, mi, o);
            if (mo > m || (mo == m && mio < mi)) { m = mo; mi = mio; }
            s1 += __shfl_down_sync(0xffffffffu, s1, o);
            s2 += __shfl_down_sync(0xffffffffu, s2, o);
            se += __shfl_down_sync(0xffffffffu, se, o);
        }
        if (lane == 0) {
            z1inv[warp] = 1.f / s1;
            z2inv[warp] = 1.f / s2;
            entp[warp] = se / s2 - logf(s2);
            atomicAdd(&g_counts[mi], 1);
            out[33554437ULL + row0 + warp] = (float)mi;
        }
    }
    __syncthreads();
    if (tid == 0) {
        float e = 0.f;
#pragma unroll
        for (int w = 0; w < 8; ++w) e += entp[w];
        atomicAdd(&g_ent, (double)e);
    }
#pragma unroll
    for (int k = 0; k < 4; ++k) {
        int j = tid + k * 256;
        float accp = 0.f;
#pragma unroll
        for (int r = 0; r < 8; ++r) {
            float v = sl[r][j];
            float w = expf(v) * z1inv[r];
            __nv_bfloat16 h = __float2bfloat16(w);
            size_t idx = (row0 + r) * NB + j;
            g_attn_hi[idx] = h;
            g_attn_lo[idx] = __float2bfloat16(w - __bfloat162float(h));
            accp = fmaf(expf(v * 100.0f), z2inv[r], accp);
        }
        atomicAdd(&g_avgp[(blockIdx.x & 31) * NB + j], accp);
    }
}

// ---------------- K5: z_q via mma.sync bf16 split (3 products, fp32 accum) ----------------
// Block: 256 thr (8 warps, 2x4), block tile 128(M) x 256(N), warp tile 64x64.
// K = 1024 in 32 chunks of 32. SMEM rows padded to 80B for conflict-free b32 frag loads.
#define ZA_HI 0
#define ZA_LO 10240
#define ZB_HI 20480
#define ZB_LO 40960
#define ZQ_SMEM 61440

__device__ __forceinline__ void mma16816(float* d, const uint32_t* a,
                                         uint32_t b0, uint32_t b1) {
    asm volatile(
        "mma.sync.aligned.m16n8k16.row.col.f32.bf16.bf16.f32 "
        "{%0,%1,%2,%3}, {%4,%5,%6,%7}, {%8,%9}, {%0,%1,%2,%3};"
        : "+f"(d[0]), "+f"(d[1]), "+f"(d[2]), "+f"(d[3])
        : "r"(a[0]), "r"(a[1]), "r"(a[2]), "r"(a[3]), "r"(b0), "r"(b1));
}

extern __shared__ char zq_sm[];

__global__ void __launch_bounds__(256, 1) zq_mma_kernel(const float* __restrict__ x,
                                                        float* __restrict__ out)
{
    char* sm = zq_sm;
    const int tid = threadIdx.x;
    const int w = tid >> 5, lane = tid & 31;
    const int r0 = blockIdx.y * 128;           // M tile (rows of attn)
    const int c0 = blockIdx.x * 256;           // N tile (cols of cb)
    const int n = r0 >> 10, t0 = r0 & 1023;
    const int wm = w >> 2, wn = w & 3;         // warp grid 2x4
    const int g = lane >> 2, tq = lane & 3;

    float acc[4][8][4];
#pragma unroll
    for (int i = 0; i < 4; ++i)
#pragma unroll
        for (int j = 0; j < 8; ++j)
#pragma unroll
            for (int v = 0; v < 4; ++v) acc[i][j][v] = 0.f;

    const int lr = tid >> 2;                   // 0..63
    const int lu = tid & 3;                    // 16B unit within 64B row

    for (int kc = 0; kc < 32; ++kc) {
        // stage A (attn hi/lo): 128 rows x 32 k
#pragma unroll
        for (int p = 0; p < 2; ++p) {
            int r = lr + p * 64;
            size_t gidx = (size_t)(r0 + r) * NB + kc * 32 + lu * 8;
            *(uint4*)(sm + ZA_HI + r * 80 + lu * 16) = *(const uint4*)(g_attn_hi + gidx);
            *(uint4*)(sm + ZA_LO + r * 80 + lu * 16) = *(const uint4*)(g_attn_lo + gidx);
        }
        // stage B (cbT hi/lo): 256 rows x 32 k
#pragma unroll
        for (int p = 0; p < 4; ++p) {
            int c = lr + p * 64;
            size_t gidx = (size_t)(c0 + c) * NB + kc * 32 + lu * 8;
            *(uint4*)(sm + ZB_HI + c * 80 + lu * 16) = *(const uint4*)(g_cbT_hi + gidx);
            *(uint4*)(sm + ZB_LO + c * 80 + lu * 16) = *(const uint4*)(g_cbT_lo + gidx);
        }
        __syncthreads();

#pragma unroll
        for (int ks = 0; ks < 2; ++ks) {
            const int kb = (ks * 16 + 2 * tq) * 2;   // byte offset within 64B row
            uint32_t ah[4][4], al[4][4];
#pragma unroll
            for (int mf = 0; mf < 4; ++mf) {
                int row = (wm * 64 + mf * 16 + g) * 80;
                ah[mf][0] = *(const uint32_t*)(sm + ZA_HI + row + kb);
                ah[mf][1] = *(const uint32_t*)(sm + ZA_HI + row + 640 + kb);
                ah[mf][2] = *(const uint32_t*)(sm + ZA_HI + row + kb + 16);
                ah[mf][3] = *(const uint32_t*)(sm + ZA_HI + row + 640 + kb + 16);
                al[mf][0] = *(const uint32_t*)(sm + ZA_LO + row + kb);
                al[mf][1] = *(const uint32_t*)(sm + ZA_LO + row + 640 + kb);
                al[mf][2] = *(const uint32_t*)(sm + ZA_LO + row + kb + 16);
                al[mf][3] = *(const uint32_t*)(sm + ZA_LO + row + 640 + kb + 16);
            }
#pragma unroll
            for (int nf = 0; nf < 8; ++nf) {
                int row = (wn * 64 + nf * 8 + g) * 80;
                uint32_t bh0 = *(const uint32_t*)(sm + ZB_HI + row + kb);
                uint32_t bh1 = *(const uint32_t*)(sm + ZB_HI + row + kb + 16);
                uint32_t bl0 = *(const uint32_t*)(sm + ZB_LO + row + kb);
                uint32_t bl1 = *(const uint32_t*)(sm + ZB_LO + row + kb + 16);
#pragma unroll
                for (int mf = 0; mf < 4; ++mf) {
                    mma16816(acc[mf][nf], ah[mf], bh0, bh1);
                    mma16816(acc[mf][nf], ah[mf], bl0, bl1);
                    mma16816(acc[mf][nf], al[mf], bh0, bh1);
                }
            }
        }
        __syncthreads();
    }

    // ---- epilogue: per-warp transpose -> coalesced (c,t) stores + vq ----
    float* sfrag = (float*)sm + w * 64 * 9;    // 64x9 fp32 per warp (18KB total)
    float vq = 0.f;
    const int tbase = t0 + wm * 64;
    const size_t obase = (size_t)n * CD * TT;
#pragma unroll 1
    for (int nf = 0; nf < 8; ++nf) {
        __syncwarp();
#pragma unroll
        for (int mf = 0; mf < 4; ++mf) {
            int rr = mf * 16 + g;
            sfrag[rr * 9 + 2 * tq]       = acc[mf][nf][0];
            sfrag[rr * 9 + 2 * tq + 1]   = acc[mf][nf][1];
            sfrag[(rr + 8) * 9 + 2 * tq]     = acc[mf][nf][2];
            sfrag[(rr + 8) * 9 + 2 * tq + 1] = acc[mf][nf][3];
        }
        __syncwarp();
#pragma unroll
        for (int col = 0; col < 8; ++col) {
            int c = c0 + wn * 64 + nf * 8 + col;
#pragma unroll
            for (int i = 0; i < 2; ++i) {
                int row = i * 32 + lane;
                float z = sfrag[row * 9 + col];
                size_t o = obase + (size_t)c * TT + tbase + row;
                float xv = x[o];
                out[o] = z;
                float d = z - xv;
                vq = fmaf(d, d, vq);
            }
        }
    }
    // block reduce vq
#pragma unroll
    for (int o = 16; o; o >>= 1) vq += __shfl_down_sync(0xffffffffu, vq, o);
    __syncthreads();
    float* red = (float*)sm;
    if (lane == 0) red[w] = vq;
    __syncthreads();
    if (tid == 0) {
        float s = 0.f;
#pragma unroll
        for (int i = 0; i < 8; ++i) s += red[i];
        atomicAdd(&g_vq, (double)s);
    }
}

// ---------------- K6: scalars ----------------
__global__ void finalize_kernel(float* __restrict__ out)
{
    const int j = threadIdx.x;
    double aps = 0.0;
#pragma unroll
    for (int s = 0; s < 32; ++s) aps += (double)g_avgp[s * NB + j];
    float ap = (float)(aps * (1.0 / 65536.0));
    float t1 = ap * logf(ap + 1e-5f);
    float pr = (float)g_counts[j] * (1.f / 65536.f);
    float t2 = pr * logf(pr + 1e-7f);

    __shared__ double r1[1024];
    __shared__ double r2[1024];
    r1[j] = (double)t1;
    r2[j] = (double)t2;
    __syncthreads();
    for (int s = 512; s >= 1; s >>= 1) {
        if (j < s) { r1[j] += r1[j + s]; r2[j] += r2[j + s]; }
        __syncthreads();
    }
    if (j == 0) {
        float avg_entropy = -(float)r1[0];
        float sample_entropy = -(float)(g_ent * (1.0 / 65536.0));
        out[33554432] = sample_entropy;
        out[33554433] = avg_entropy;
        out[33554434] = sample_entropy - avg_entropy;
        out[33554435] = expf(-(float)r2[0]);
        out[33554436] = (float)(g_vq * (1.0 / 33554432.0));
    }
}

// ---------------- launch ----------------
extern "C" void kernel_launch(void* const* d_in, const int* in_sizes, int n_in,
                              void* d_out, int out_size)
{
    const float* x  = (const float*)d_in[0];
    const float* cb = (const float*)d_in[1];
    const float* Wq = (const float*)d_in[2];
    const float* Wk = (const float*)d_in[3];
    float* out = (float*)d_out;

    cudaFuncSetAttribute(zq_mma_kernel, cudaFuncAttributeMaxDynamicSharedMemorySize, ZQ_SMEM);

    init_kernel<<<256, 256>>>();
    kproj_kernel<<<dim3(8, 16), 256>>>(cb, Wk);
    ksumsq_kernel<<<128, 256>>>();
    knorm_kernel<<<2048, 256>>>();
    qproj_kernel<<<dim3(8, 1024), 256>>>(x, Wq);
    qnorm_kernel<<<8192, 256>>>();
    logits_kernel<<<dim3(16, 1024), 256>>>();
    cbt_kernel<<<2048, 256>>>(cb);
    rowpass_kernel<<<8192, 256>>>(out);
    zq_mma_kernel<<<dim3(2, 512), 256, ZQ_SMEM>>>(x, out);
    finalize_kernel<<<1, 1024>>>(out);
}

// round 7
// speedup vs baseline: 1.0766x; 1.0075x over previous
#include <cuda_runtime.h>
#include <cuda_bf16.h>
#include <cstdint>

#define NB   1024          // nb_code
#define CD   512           // C
#define AD   512           // attn_dim
#define TT   1024          // T
#define NT   65536         // N*T

// ---------------- scratch (device globals: allocation-free) ----------------
__device__ float  g_ku[NB * AD];              // unnormalized k
__device__ float  g_kdenom[NB];               // |k_j| + 1e-8
__device__ float  g_knT[AD * NB];             // normalized k, transposed [a][j]
__device__ float  g_q[(size_t)NT * AD];       // q; normalized in place by qnorm
__device__ float  g_logits[(size_t)NT * NB];  // logits
__device__ __align__(16) __nv_bfloat16 g_attn_d[(size_t)NT * NB];  // bf16(attn - 2^-10)
__device__ __align__(16) __nv_bfloat16 g_cbT_hi[CD * NB];          // bf16 cb^T [c][j]
__device__ float  g_cmean[CD];                // 2^-10 * colsum(cb), fp32 from double
__device__ float  g_avgp[32 * NB];            // avg_probs partial slots
__device__ int    g_counts[NB];
__device__ double g_ent;
__device__ double g_vq;

// ---------------- init ----------------
__global__ void init_kernel() {
    int i = blockIdx.x * 256 + threadIdx.x;
    if (i < NB) g_counts[i] = 0;
    if (i < 32 * NB) g_avgp[i] = 0.f;
    if (i == 0) { g_ent = 0.0; g_vq = 0.0; }
}

// ---------------- SIMT GEMM tile machinery (exact path, unchanged) ----------------
__device__ __forceinline__ void gemm_rowmajorA(
    const float* __restrict__ A, int lda,
    const float* __restrict__ B, int ldb,
    int ksteps, float (&acc)[4][4])
{
    __shared__ __align__(16) float As[32][68];
    __shared__ __align__(16) float Bs[32][68];
    const int tid = threadIdx.x;
    const int aK = tid & 31, aR = tid >> 5;
    const int bC = tid & 63, bK = tid >> 6;
    const int tx = tid & 15, ty = tid >> 4;
    for (int kt = 0; kt < ksteps; ++kt) {
#pragma unroll
        for (int p = 0; p < 8; ++p)
            As[aK][aR + p * 8] = A[(size_t)(aR + p * 8) * lda + aK];
#pragma unroll
        for (int p = 0; p < 8; ++p)
            Bs[bK + p * 4][bC] = B[(size_t)(bK + p * 4) * ldb + bC];
        __syncthreads();
#pragma unroll
        for (int kk = 0; kk < 32; ++kk) {
            float4 a4 = *(const float4*)&As[kk][ty * 4];
            float4 b4 = *(const float4*)&Bs[kk][tx * 4];
            float av[4] = {a4.x, a4.y, a4.z, a4.w};
            float bv[4] = {b4.x, b4.y, b4.z, b4.w};
#pragma unroll
            for (int i = 0; i < 4; ++i)
#pragma unroll
                for (int j = 0; j < 4; ++j)
                    acc[i][j] = fmaf(av[i], bv[j], acc[i][j]);
        }
        __syncthreads();
        A += 32;
        B += (size_t)32 * ldb;
    }
}

__device__ __forceinline__ void gemm_xA(
    const float* __restrict__ A,
    const float* __restrict__ B, int ldb,
    int ksteps, float (&acc)[4][4])
{
    __shared__ __align__(16) float As[32][68];
    __shared__ __align__(16) float Bs[32][68];
    const int tid = threadIdx.x;
    const int aR = tid & 63, aK = tid >> 6;
    const int bC = tid & 63, bK = tid >> 6;
    const int tx = tid & 15, ty = tid >> 4;
    for (int kt = 0; kt < ksteps; ++kt) {
#pragma unroll
        for (int p = 0; p < 8; ++p)
            As[aK + p * 4][aR] = A[(size_t)(aK + p * 4) * TT + aR];
#pragma unroll
        for (int p = 0; p < 8; ++p)
            Bs[bK + p * 4][bC] = B[(size_t)(bK + p * 4) * ldb + bC];
        __syncthreads();
#pragma unroll
        for (int kk = 0; kk < 32; ++kk) {
            float4 a4 = *(const float4*)&As[kk][ty * 4];
            float4 b4 = *(const float4*)&Bs[kk][tx * 4];
            float av[4] = {a4.x, a4.y, a4.z, a4.w};
            float bv[4] = {b4.x, b4.y, b4.z, b4.w};
#pragma unroll
            for (int i = 0; i < 4; ++i)
#pragma unroll
                for (int j = 0; j < 4; ++j)
                    acc[i][j] = fmaf(av[i], bv[j], acc[i][j]);
        }
        __syncthreads();
        A += (size_t)32 * TT;
        B += (size_t)32 * ldb;
    }
}

// ---------------- K1: ku = codebook @ Wk ----------------
__global__ void __launch_bounds__(256) kproj_kernel(const float* __restrict__ cb,
                                                    const float* __restrict__ Wk)
{
    float acc[4][4] = {};
    const int j0 = blockIdx.y * 64, a0 = blockIdx.x * 64;
    gemm_rowmajorA(cb + (size_t)j0 * CD, CD, Wk + a0, AD, CD / 32, acc);
    const int tid = threadIdx.x, tx = tid & 15, ty = tid >> 4;
#pragma unroll
    for (int i = 0; i < 4; ++i) {
        int row = ty * 4 + i;
        float4 v = make_float4(acc[i][0], acc[i][1], acc[i][2], acc[i][3]);
        *(float4*)&g_ku[(size_t)(j0 + row) * AD + a0 + tx * 4] = v;
    }
}

__global__ void __launch_bounds__(256) ksumsq_kernel() {
    const int warp = threadIdx.x >> 5, lane = threadIdx.x & 31;
    const int j = blockIdx.x * 8 + warp;
    const float* k = g_ku + (size_t)j * AD;
    double s = 0.0;
#pragma unroll
    for (int i = 0; i < 16; ++i) { double t = (double)k[lane + i * 32]; s += t * t; }
#pragma unroll
    for (int o = 16; o; o >>= 1) s += __shfl_down_sync(0xffffffffu, s, o);
    if (lane == 0) g_kdenom[j] = __fsqrt_rn((float)s) + 1e-8f;
}

__global__ void knorm_kernel() {
    int idx = blockIdx.x * 256 + threadIdx.x;
    int j = idx >> 9, a = idx & 511;
    g_knT[(size_t)a * NB + j] = __fdiv_rn(g_ku[idx], g_kdenom[j]);
}

// ---------------- K2: q = xf @ Wq ----------------
__global__ void __launch_bounds__(256) qproj_kernel(const float* __restrict__ x,
                                                    const float* __restrict__ Wq)
{
    float acc[4][4] = {};
    const int r0 = blockIdx.y * 64, a0 = blockIdx.x * 64;
    const int n = r0 >> 10, t0 = r0 & 1023;
    gemm_xA(x + (size_t)n * CD * TT + t0, Wq + a0, AD, CD / 32, acc);
    const int tid = threadIdx.x, tx = tid & 15, ty = tid >> 4;
#pragma unroll
    for (int i = 0; i < 4; ++i) {
        int row = ty * 4 + i;
        float4 v = make_float4(acc[i][0], acc[i][1], acc[i][2], acc[i][3]);
        *(float4*)&g_q[(size_t)(r0 + row) * AD + a0 + tx * 4] = v;
    }
}

__global__ void __launch_bounds__(256) qnorm_kernel() {
    const int warp = threadIdx.x >> 5, lane = threadIdx.x & 31;
    const size_t r = (size_t)blockIdx.x * 8 + warp;
    float* q = g_q + r * AD;
    float v[16];
    double s = 0.0;
#pragma unroll
    for (int i = 0; i < 16; ++i) { v[i] = q[lane + i * 32]; s += (double)v[i] * v[i]; }
#pragma unroll
    for (int o = 16; o; o >>= 1) s += __shfl_down_sync(0xffffffffu, s, o);
    s = __shfl_sync(0xffffffffu, s, 0);
    float denom = __fsqrt_rn((float)s) + 1e-8f;
#pragma unroll
    for (int i = 0; i < 16; ++i) q[lane + i * 32] = __fdiv_rn(v[i], denom);
}

// ---------------- K3: logits ----------------
__global__ void __launch_bounds__(256) logits_kernel()
{
    float acc[4][4] = {};
    const int r0 = blockIdx.y * 64, j0 = blockIdx.x * 64;
    gemm_rowmajorA(g_q + (size_t)r0 * AD, AD, g_knT + j0, NB, AD / 32, acc);
    const int tid = threadIdx.x, tx = tid & 15, ty = tid >> 4;
    const float SQ = 22.62741699796952f;
#pragma unroll
    for (int i = 0; i < 4; ++i) {
        int r = r0 + ty * 4 + i;
        float4 v = make_float4(__fdiv_rn(acc[i][0], SQ), __fdiv_rn(acc[i][1], SQ),
                               __fdiv_rn(acc[i][2], SQ), __fdiv_rn(acc[i][3], SQ));
        *(float4*)&g_logits[(size_t)r * NB + j0 + tx * 4] = v;
    }
}

// ---------------- cbT bf16 + column means ----------------
__global__ void cbt_kernel(const float* __restrict__ cb) {
    int idx = blockIdx.x * 256 + threadIdx.x;   // 524288: idx = c*NB + j
    int c = idx >> 10, j = idx & 1023;
    g_cbT_hi[idx] = __float2bfloat16(cb[(size_t)j * CD + c]);
}

// g_cmean[c] = 2^-10 * sum_j cb[j][c]  (double accumulation, fp32 store)
__global__ void colsum_kernel(const float* __restrict__ cb) {
    int c = blockIdx.x * 256 + threadIdx.x;     // grid 2 -> 512 cols
    double s = 0.0;
    for (int j = 0; j < NB; ++j) s += (double)cb[(size_t)j * CD + c];
    g_cmean[c] = (float)(s * 0.0009765625);
}

// ---------------- K4: row pass; emits delta = attn - 2^-10 as bf16 ----------------
__global__ void __launch_bounds__(256) rowpass_kernel(float* __restrict__ out)
{
    __shared__ float sl[8][1024];
    __shared__ float z1inv[8], z2inv[8], entp[8];
    const int tid = threadIdx.x;
    const size_t row0 = (size_t)blockIdx.x * 8;
    const float* src = g_logits + row0 * NB;
#pragma unroll
    for (int p = 0; p < 32; ++p)
        ((float*)sl)[p * 256 + tid] = src[p * 256 + tid];
    __syncthreads();

    const int warp = tid >> 5, lane = tid & 31;
    {
        float m = -1e30f; int mi = 0;
        float s1 = 0.f, s2 = 0.f, se = 0.f;
        for (int j = lane; j < 1024; j += 32) {
            float v = sl[warp][j];
            if (v > m) { m = v; mi = j; }
            s1 += expf(v);
            float l2 = v * 100.0f;
            float e2 = expf(l2);
            s2 += e2;
            se = fmaf(e2, l2, se);
        }
#pragma unroll
        for (int o = 16; o; o >>= 1) {
            float mo = __shfl_down_sync(0xffffffffu, m, o);
            int mio = __shfl_down_sync(0xffffffffu, mi, o);
            if (mo > m || (mo == m && mio < mi)) { m = mo; mi = mio; }
            s1 += __shfl_down_sync(0xffffffffu, s1, o);
            s2 += __shfl_down_sync(0xffffffffu, s2, o);
            se += __shfl_down_sync(0xffffffffu, se, o);
        }
        if (lane == 0) {
            z1inv[warp] = 1.f / s1;
            z2inv[warp] = 1.f / s2;
            entp[warp] = se / s2 - logf(s2);
            atomicAdd(&g_counts[mi], 1);
            out[33554437ULL + row0 + warp] = (float)mi;
        }
    }
    __syncthreads();
    if (tid == 0) {
        float e = 0.f;
#pragma unroll
        for (int w = 0; w < 8; ++w) e += entp[w];
        atomicAdd(&g_ent, (double)e);
    }
#pragma unroll
    for (int k = 0; k < 4; ++k) {
        int j = tid + k * 256;
        float accp = 0.f;
#pragma unroll
        for (int r = 0; r < 8; ++r) {
            float v = sl[r][j];
            float w = expf(v) * z1inv[r];
            // attn in [2^-11, 2^-9] always -> Sterbenz: exact fp32 delta
            float d = w - 0.0009765625f;
            g_attn_d[(row0 + r) * NB + j] = __float2bfloat16(d);
            accp = fmaf(expf(v * 100.0f), z2inv[r], accp);
        }
        atomicAdd(&g_avgp[(blockIdx.x & 31) * NB + j], accp);
    }
}

// ---------------- K5: z_q = cmean + delta @ cb^T  (single bf16 MMA product) ----------------
// Block: 256 thr (8 warps, 2x4), block tile 128(M) x 256(N), warp tile 64x64.
// K = 1024 in 32 chunks of 32. SMEM rows padded to 80B for conflict-free b32 frag loads.
#define ZA_D  0
#define ZB_H  10240
#define ZQ_SMEM 30720

__device__ __forceinline__ void mma16816(float* d, const uint32_t* a,
                                         uint32_t b0, uint32_t b1) {
    asm volatile(
        "mma.sync.aligned.m16n8k16.row.col.f32.bf16.bf16.f32 "
        "{%0,%1,%2,%3}, {%4,%5,%6,%7}, {%8,%9}, {%0,%1,%2,%3};"
        : "+f"(d[0]), "+f"(d[1]), "+f"(d[2]), "+f"(d[3])
        : "r"(a[0]), "r"(a[1]), "r"(a[2]), "r"(a[3]), "r"(b0), "r"(b1));
}

extern __shared__ char zq_sm[];

__global__ void __launch_bounds__(256, 1) zq_mma_kernel(const float* __restrict__ x,
                                                        float* __restrict__ out)
{
    char* sm = zq_sm;
    const int tid = threadIdx.x;
    const int w = tid >> 5, lane = tid & 31;
    const int r0 = blockIdx.y * 128;           // M tile (rows of attn)
    const int c0 = blockIdx.x * 256;           // N tile (cols of cb)
    const int n = r0 >> 10, t0 = r0 & 1023;
    const int wm = w >> 2, wn = w & 3;         // warp grid 2x4
    const int g = lane >> 2, tq = lane & 3;

    float acc[4][8][4];
#pragma unroll
    for (int i = 0; i < 4; ++i)
#pragma unroll
        for (int j = 0; j < 8; ++j)
#pragma unroll
            for (int v = 0; v < 4; ++v) acc[i][j][v] = 0.f;

    const int lr = tid >> 2;                   // 0..63
    const int lu = tid & 3;                    // 16B unit within 64B row

    for (int kc = 0; kc < 32; ++kc) {
        // stage A (delta): 128 rows x 32 k
#pragma unroll
        for (int p = 0; p < 2; ++p) {
            int r = lr + p * 64;
            size_t gidx = (size_t)(r0 + r) * NB + kc * 32 + lu * 8;
            *(uint4*)(sm + ZA_D + r * 80 + lu * 16) = *(const uint4*)(g_attn_d + gidx);
        }
        // stage B (cbT hi): 256 rows x 32 k
#pragma unroll
        for (int p = 0; p < 4; ++p) {
            int c = lr + p * 64;
            size_t gidx = (size_t)(c0 + c) * NB + kc * 32 + lu * 8;
            *(uint4*)(sm + ZB_H + c * 80 + lu * 16) = *(const uint4*)(g_cbT_hi + gidx);
        }
        __syncthreads();

#pragma unroll
        for (int ks = 0; ks < 2; ++ks) {
            const int kb = (ks * 16 + 2 * tq) * 2;   // byte offset within 64B row
            uint32_t ad[4][4];
#pragma unroll
            for (int mf = 0; mf < 4; ++mf) {
                int row = (wm * 64 + mf * 16 + g) * 80;
                ad[mf][0] = *(const uint32_t*)(sm + ZA_D + row + kb);
                ad[mf][1] = *(const uint32_t*)(sm + ZA_D + row + 640 + kb);
                ad[mf][2] = *(const uint32_t*)(sm + ZA_D + row + kb + 16);
                ad[mf][3] = *(const uint32_t*)(sm + ZA_D + row + 640 + kb + 16);
            }
#pragma unroll
            for (int nf = 0; nf < 8; ++nf) {
                int row = (wn * 64 + nf * 8 + g) * 80;
                uint32_t bh0 = *(const uint32_t*)(sm + ZB_H + row + kb);
                uint32_t bh1 = *(const uint32_t*)(sm + ZB_H + row + kb + 16);
#pragma unroll
                for (int mf = 0; mf < 4; ++mf)
                    mma16816(acc[mf][nf], ad[mf], bh0, bh1);
            }
        }
        __syncthreads();
    }

    // ---- epilogue: per-warp transpose -> coalesced (c,t) stores + mean + vq ----
    float* sfrag = (float*)sm + w * 64 * 9;    // 64x9 fp32 per warp (18KB total)
    float vq = 0.f;
    const int tbase = t0 + wm * 64;
    const size_t obase = (size_t)n * CD * TT;
#pragma unroll 1
    for (int nf = 0; nf < 8; ++nf) {
        __syncwarp();
#pragma unroll
        for (int mf = 0; mf < 4; ++mf) {
            int rr = mf * 16 + g;
            sfrag[rr * 9 + 2 * tq]       = acc[mf][nf][0];
            sfrag[rr * 9 + 2 * tq + 1]   = acc[mf][nf][1];
            sfrag[(rr + 8) * 9 + 2 * tq]     = acc[mf][nf][2];
            sfrag[(rr + 8) * 9 + 2 * tq + 1] = acc[mf][nf][3];
        }
        __syncwarp();
#pragma unroll
        for (int col = 0; col < 8; ++col) {
            int c = c0 + wn * 64 + nf * 8 + col;
            float cm = g_cmean[c];
#pragma unroll
            for (int i = 0; i < 2; ++i) {
                int row = i * 32 + lane;
                float z = sfrag[row * 9 + col] + cm;
                size_t o = obase + (size_t)c * TT + tbase + row;
                float xv = x[o];
                out[o] = z;
                float d = z - xv;
                vq = fmaf(d, d, vq);
            }
        }
    }
    // block reduce vq
#pragma unroll
    for (int o = 16; o; o >>= 1) vq += __shfl_down_sync(0xffffffffu, vq, o);
    __syncthreads();
    float* red = (float*)sm;
    if (lane == 0) red[w] = vq;
    __syncthreads();
    if (tid == 0) {
        float s = 0.f;
#pragma unroll
        for (int i = 0; i < 8; ++i) s += red[i];
        atomicAdd(&g_vq, (double)s);
    }
}

// ---------------- K6: scalars ----------------
__global__ void finalize_kernel(float* __restrict__ out)
{
    const int j = threadIdx.x;
    double aps = 0.0;
#pragma unroll
    for (int s = 0; s < 32; ++s) aps += (double)g_avgp[s * NB + j];
    float ap = (float)(aps * (1.0 / 65536.0));
    float t1 = ap * logf(ap + 1e-5f);
    float pr = (float)g_counts[j] * (1.f / 65536.f);
    float t2 = pr * logf(pr + 1e-7f);

    __shared__ double r1[1024];
    __shared__ double r2[1024];
    r1[j] = (double)t1;
    r2[j] = (double)t2;
    __syncthreads();
    for (int s = 512; s >= 1; s >>= 1) {
        if (j < s) { r1[j] += r1[j + s]; r2[j] += r2[j + s]; }
        __syncthreads();
    }
    if (j == 0) {
        float avg_entropy = -(float)r1[0];
        float sample_entropy = -(float)(g_ent * (1.0 / 65536.0));
        out[33554432] = sample_entropy;
        out[33554433] = avg_entropy;
        out[33554434] = sample_entropy - avg_entropy;
        out[33554435] = expf(-(float)r2[0]);
        out[33554436] = (float)(g_vq * (1.0 / 33554432.0));
    }
}

// ---------------- launch ----------------
extern "C" void kernel_launch(void* const* d_in, const int* in_sizes, int n_in,
                              void* d_out, int out_size)
{
    const float* x  = (const float*)d_in[0];
    const float* cb = (const float*)d_in[1];
    const float* Wq = (const float*)d_in[2];
    const float* Wk = (const float*)d_in[3];
    float* out = (float*)d_out;

    cudaFuncSetAttribute(zq_mma_kernel, cudaFuncAttributeMaxDynamicSharedMemorySize, ZQ_SMEM);

    init_kernel<<<256, 256>>>();
    kproj_kernel<<<dim3(8, 16), 256>>>(cb, Wk);
    ksumsq_kernel<<<128, 256>>>();
    knorm_kernel<<<2048, 256>>>();
    qproj_kernel<<<dim3(8, 1024), 256>>>(x, Wq);
    qnorm_kernel<<<8192, 256>>>();
    logits_kernel<<<dim3(16, 1024), 256>>>();
    cbt_kernel<<<2048, 256>>>(cb);
    colsum_kernel<<<2, 256>>>(cb);
    rowpass_kernel<<<8192, 256>>>(out);
    zq_mma_kernel<<<dim3(2, 512), 256, ZQ_SMEM>>>(x, out);
    finalize_kernel<<<1, 1024>>>(out);
}

// round 8
// speedup vs baseline: 1.3460x; 1.2502x over previous
#include <cuda_runtime.h>
#include <cuda_bf16.h>
#include <cstdint>

#define NB   1024          // nb_code
#define CD   512           // C
#define AD   512           // attn_dim
#define TT   1024          // T
#define NT   65536         // N*T

// ---------------- scratch (device globals: allocation-free) ----------------
__device__ float  g_ku[NB * AD];              // unnormalized k
__device__ float  g_kdenom[NB];               // |k_j| + 1e-8
__device__ float  g_knT[AD * NB];             // normalized k, transposed [a][j]
__device__ float  g_q[(size_t)NT * AD];       // q; normalized in place by qnorm
__device__ float  g_logits[(size_t)NT * NB];  // logits
__device__ __align__(16) __nv_bfloat16 g_attn_d[(size_t)NT * NB];  // bf16(attn - 2^-10)
__device__ __align__(16) __nv_bfloat16 g_cbT_hi[CD * NB];          // bf16 cb^T [c][j]
__device__ float  g_cmean[CD];                // 2^-10 * colsum(cb), fp32 from double
__device__ float  g_avgp[32 * NB];            // avg_probs partial slots
__device__ int    g_counts[NB];
__device__ double g_ent;
__device__ double g_vq;

// ---------------- init ----------------
__global__ void init_kernel() {
    int i = blockIdx.x * 256 + threadIdx.x;
    if (i < NB) g_counts[i] = 0;
    if (i < 32 * NB) g_avgp[i] = 0.f;
    if (i == 0) { g_ent = 0.0; g_vq = 0.0; }
}

// ---------------- SIMT GEMM tile machinery (exact path, unchanged) ----------------
__device__ __forceinline__ void gemm_rowmajorA(
    const float* __restrict__ A, int lda,
    const float* __restrict__ B, int ldb,
    int ksteps, float (&acc)[4][4])
{
    __shared__ __align__(16) float As[32][68];
    __shared__ __align__(16) float Bs[32][68];
    const int tid = threadIdx.x;
    const int aK = tid & 31, aR = tid >> 5;
    const int bC = tid & 63, bK = tid >> 6;
    const int tx = tid & 15, ty = tid >> 4;
    for (int kt = 0; kt < ksteps; ++kt) {
#pragma unroll
        for (int p = 0; p < 8; ++p)
            As[aK][aR + p * 8] = A[(size_t)(aR + p * 8) * lda + aK];
#pragma unroll
        for (int p = 0; p < 8; ++p)
            Bs[bK + p * 4][bC] = B[(size_t)(bK + p * 4) * ldb + bC];
        __syncthreads();
#pragma unroll
        for (int kk = 0; kk < 32; ++kk) {
            float4 a4 = *(const float4*)&As[kk][ty * 4];
            float4 b4 = *(const float4*)&Bs[kk][tx * 4];
            float av[4] = {a4.x, a4.y, a4.z, a4.w};
            float bv[4] = {b4.x, b4.y, b4.z, b4.w};
#pragma unroll
            for (int i = 0; i < 4; ++i)
#pragma unroll
                for (int j = 0; j < 4; ++j)
                    acc[i][j] = fmaf(av[i], bv[j], acc[i][j]);
        }
        __syncthreads();
        A += 32;
        B += (size_t)32 * ldb;
    }
}

__device__ __forceinline__ void gemm_xA(
    const float* __restrict__ A,
    const float* __restrict__ B, int ldb,
    int ksteps, float (&acc)[4][4])
{
    __shared__ __align__(16) float As[32][68];
    __shared__ __align__(16) float Bs[32][68];
    const int tid = threadIdx.x;
    const int aR = tid & 63, aK = tid >> 6;
    const int bC = tid & 63, bK = tid >> 6;
    const int tx = tid & 15, ty = tid >> 4;
    for (int kt = 0; kt < ksteps; ++kt) {
#pragma unroll
        for (int p = 0; p < 8; ++p)
            As[aK + p * 4][aR] = A[(size_t)(aK + p * 4) * TT + aR];
#pragma unroll
        for (int p = 0; p < 8; ++p)
            Bs[bK + p * 4][bC] = B[(size_t)(bK + p * 4) * ldb + bC];
        __syncthreads();
#pragma unroll
        for (int kk = 0; kk < 32; ++kk) {
            float4 a4 = *(const float4*)&As[kk][ty * 4];
            float4 b4 = *(const float4*)&Bs[kk][tx * 4];
            float av[4] = {a4.x, a4.y, a4.z, a4.w};
            float bv[4] = {b4.x, b4.y, b4.z, b4.w};
#pragma unroll
            for (int i = 0; i < 4; ++i)
#pragma unroll
                for (int j = 0; j < 4; ++j)
                    acc[i][j] = fmaf(av[i], bv[j], acc[i][j]);
        }
        __syncthreads();
        A += (size_t)32 * TT;
        B += (size_t)32 * ldb;
    }
}

// ---------------- K1: ku = codebook @ Wk ----------------
__global__ void __launch_bounds__(256) kproj_kernel(const float* __restrict__ cb,
                                                    const float* __restrict__ Wk)
{
    float acc[4][4] = {};
    const int j0 = blockIdx.y * 64, a0 = blockIdx.x * 64;
    gemm_rowmajorA(cb + (size_t)j0 * CD, CD, Wk + a0, AD, CD / 32, acc);
    const int tid = threadIdx.x, tx = tid & 15, ty = tid >> 4;
#pragma unroll
    for (int i = 0; i < 4; ++i) {
        int row = ty * 4 + i;
        float4 v = make_float4(acc[i][0], acc[i][1], acc[i][2], acc[i][3]);
        *(float4*)&g_ku[(size_t)(j0 + row) * AD + a0 + tx * 4] = v;
    }
}

__global__ void __launch_bounds__(256) ksumsq_kernel() {
    const int warp = threadIdx.x >> 5, lane = threadIdx.x & 31;
    const int j = blockIdx.x * 8 + warp;
    const float* k = g_ku + (size_t)j * AD;
    double s = 0.0;
#pragma unroll
    for (int i = 0; i < 16; ++i) { double t = (double)k[lane + i * 32]; s += t * t; }
#pragma unroll
    for (int o = 16; o; o >>= 1) s += __shfl_down_sync(0xffffffffu, s, o);
    if (lane == 0) g_kdenom[j] = __fsqrt_rn((float)s) + 1e-8f;
}

__global__ void knorm_kernel() {
    int idx = blockIdx.x * 256 + threadIdx.x;
    int j = idx >> 9, a = idx & 511;
    g_knT[(size_t)a * NB + j] = __fdiv_rn(g_ku[idx], g_kdenom[j]);
}

// ---------------- K2: q = xf @ Wq ----------------
__global__ void __launch_bounds__(256) qproj_kernel(const float* __restrict__ x,
                                                    const float* __restrict__ Wq)
{
    float acc[4][4] = {};
    const int r0 = blockIdx.y * 64, a0 = blockIdx.x * 64;
    const int n = r0 >> 10, t0 = r0 & 1023;
    gemm_xA(x + (size_t)n * CD * TT + t0, Wq + a0, AD, CD / 32, acc);
    const int tid = threadIdx.x, tx = tid & 15, ty = tid >> 4;
#pragma unroll
    for (int i = 0; i < 4; ++i) {
        int row = ty * 4 + i;
        float4 v = make_float4(acc[i][0], acc[i][1], acc[i][2], acc[i][3]);
        *(float4*)&g_q[(size_t)(r0 + row) * AD + a0 + tx * 4] = v;
    }
}

__global__ void __launch_bounds__(256) qnorm_kernel() {
    const int warp = threadIdx.x >> 5, lane = threadIdx.x & 31;
    const size_t r = (size_t)blockIdx.x * 8 + warp;
    float* q = g_q + r * AD;
    float v[16];
    double s = 0.0;
#pragma unroll
    for (int i = 0; i < 16; ++i) { v[i] = q[lane + i * 32]; s += (double)v[i] * v[i]; }
#pragma unroll
    for (int o = 16; o; o >>= 1) s += __shfl_down_sync(0xffffffffu, s, o);
    s = __shfl_sync(0xffffffffu, s, 0);
    float denom = __fsqrt_rn((float)s) + 1e-8f;
#pragma unroll
    for (int i = 0; i < 16; ++i) q[lane + i * 32] = __fdiv_rn(v[i], denom);
}

// ---------------- K3: logits ----------------
__global__ void __launch_bounds__(256) logits_kernel()
{
    float acc[4][4] = {};
    const int r0 = blockIdx.y * 64, j0 = blockIdx.x * 64;
    gemm_rowmajorA(g_q + (size_t)r0 * AD, AD, g_knT + j0, NB, AD / 32, acc);
    const int tid = threadIdx.x, tx = tid & 15, ty = tid >> 4;
    const float SQ = 22.62741699796952f;
#pragma unroll
    for (int i = 0; i < 4; ++i) {
        int r = r0 + ty * 4 + i;
        float4 v = make_float4(__fdiv_rn(acc[i][0], SQ), __fdiv_rn(acc[i][1], SQ),
                               __fdiv_rn(acc[i][2], SQ), __fdiv_rn(acc[i][3], SQ));
        *(float4*)&g_logits[(size_t)r * NB + j0 + tx * 4] = v;
    }
}

// ---------------- cbT bf16 + column means ----------------
__global__ void cbt_kernel(const float* __restrict__ cb) {
    int idx = blockIdx.x * 256 + threadIdx.x;   // 524288: idx = c*NB + j
    int c = idx >> 10, j = idx & 1023;
    g_cbT_hi[idx] = __float2bfloat16(cb[(size_t)j * CD + c]);
}

// g_cmean[c] = 2^-10 * sum_j cb[j][c]  (double accumulation, fp32 store)
__global__ void colsum_kernel(const float* __restrict__ cb) {
    int c = blockIdx.x * 256 + threadIdx.x;     // grid 2 -> 512 cols
    double s = 0.0;
    for (int j = 0; j < NB; ++j) s += (double)cb[(size_t)j * CD + c];
    g_cmean[c] = (float)(s * 0.0009765625);
}

// ---------------- K4: row pass; emits delta = attn - 2^-10 as bf16 ----------------
__global__ void __launch_bounds__(256) rowpass_kernel(float* __restrict__ out)
{
    __shared__ float sl[8][1024];
    __shared__ float z1inv[8], z2inv[8], entp[8];
    const int tid = threadIdx.x;
    const size_t row0 = (size_t)blockIdx.x * 8;
    const float* src = g_logits + row0 * NB;
#pragma unroll
    for (int p = 0; p < 32; ++p)
        ((float*)sl)[p * 256 + tid] = src[p * 256 + tid];
    __syncthreads();

    const int warp = tid >> 5, lane = tid & 31;
    {
        float m = -1e30f; int mi = 0;
        float s1 = 0.f, s2 = 0.f, se = 0.f;
        for (int j = lane; j < 1024; j += 32) {
            float v = sl[warp][j];
            if (v > m) { m = v; mi = j; }
            s1 += expf(v);
            float l2 = v * 100.0f;
            float e2 = expf(l2);
            s2 += e2;
            se = fmaf(e2, l2, se);
        }
#pragma unroll
        for (int o = 16; o; o >>= 1) {
            float mo = __shfl_down_sync(0xffffffffu, m, o);
            int mio = __shfl_down_sync(0xffffffffu, mi, o);
            if (mo > m || (mo == m && mio < mi)) { m = mo; mi = mio; }
            s1 += __shfl_down_sync(0xffffffffu, s1, o);
            s2 += __shfl_down_sync(0xffffffffu, s2, o);
            se += __shfl_down_sync(0xffffffffu, se, o);
        }
        if (lane == 0) {
            z1inv[warp] = 1.f / s1;
            z2inv[warp] = 1.f / s2;
            entp[warp] = se / s2 - logf(s2);
            atomicAdd(&g_counts[mi], 1);
            out[33554437ULL + row0 + warp] = (float)mi;
        }
    }
    __syncthreads();
    if (tid == 0) {
        float e = 0.f;
#pragma unroll
        for (int w = 0; w < 8; ++w) e += entp[w];
        atomicAdd(&g_ent, (double)e);
    }
#pragma unroll
    for (int k = 0; k < 4; ++k) {
        int j = tid + k * 256;
        float accp = 0.f;
#pragma unroll
        for (int r = 0; r < 8; ++r) {
            float v = sl[r][j];
            float w = expf(v) * z1inv[r];
            // attn in [2^-11, 2^-9] always -> Sterbenz: exact fp32 delta
            float d = w - 0.0009765625f;
            g_attn_d[(row0 + r) * NB + j] = __float2bfloat16(d);
            accp = fmaf(expf(v * 100.0f), z2inv[r], accp);
        }
        atomicAdd(&g_avgp[(blockIdx.x & 31) * NB + j], accp);
    }
}

// ---------------- K5: z_q = cmean + delta @ cb^T (cp.async double-buffered MMA) ----------------
// Block 256 thr (8 warps 2x4), block tile 128(M) x 128(N), warp tile 64x32.
// K = 1024 in 32 chunks of 32; 2-stage cp.async pipeline; fully static epilogue.
#define ZQ_STAGE 20480
#define ZQ_SMEM  40960

__device__ __forceinline__ void mma16816(float* d, const uint32_t* a,
                                         uint32_t b0, uint32_t b1) {
    asm volatile(
        "mma.sync.aligned.m16n8k16.row.col.f32.bf16.bf16.f32 "
        "{%0,%1,%2,%3}, {%4,%5,%6,%7}, {%8,%9}, {%0,%1,%2,%3};"
        : "+f"(d[0]), "+f"(d[1]), "+f"(d[2]), "+f"(d[3])
        : "r"(a[0]), "r"(a[1]), "r"(a[2]), "r"(a[3]), "r"(b0), "r"(b1));
}

#define CP16(dst, src) \
    asm volatile("cp.async.cg.shared.global [%0], [%1], 16;" :: "r"(dst), "l"(src))
#define CP_COMMIT() asm volatile("cp.async.commit_group;" ::: "memory")
#define CP_WAIT(n)  asm volatile("cp.async.wait_group %0;" :: "n"(n) : "memory")

extern __shared__ char zq_sm[];

__global__ void __launch_bounds__(256) zq_mma_kernel(const float* __restrict__ x,
                                                     float* __restrict__ out)
{
    char* sm = zq_sm;
    const uint32_t sb = (uint32_t)__cvta_generic_to_shared(sm);
    const int tid = threadIdx.x;
    const int w = tid >> 5, lane = tid & 31;
    const int r0 = blockIdx.y * 128;           // M tile (rows of attn)
    const int c0 = blockIdx.x * 128;           // N tile (cols of cb)
    const int n = r0 >> 10, t0 = r0 & 1023;
    const int wm = w >> 2, wn = w & 3;         // warp grid 2x4
    const int g = lane >> 2, tq = lane & 3;

    float acc[4][4][4] = {};

    const int lr = tid >> 2;                   // 0..63
    const int lu = tid & 3;                    // 16B unit within 64B k-slice

    const char* gA0 = (const char*)(g_attn_d + (size_t)(r0 + lr) * NB) + lu * 16;
    const char* gA1 = (const char*)(g_attn_d + (size_t)(r0 + lr + 64) * NB) + lu * 16;
    const char* gB0 = (const char*)(g_cbT_hi + (size_t)(c0 + lr) * NB) + lu * 16;
    const char* gB1 = (const char*)(g_cbT_hi + (size_t)(c0 + lr + 64) * NB) + lu * 16;
    const uint32_t sA0 = sb + lr * 80 + lu * 16;
    const uint32_t sA1 = sb + (lr + 64) * 80 + lu * 16;
    const uint32_t sB0 = sb + 10240 + lr * 80 + lu * 16;
    const uint32_t sB1 = sb + 10240 + (lr + 64) * 80 + lu * 16;

    // prologue: stage chunks 0 and 1
    CP16(sA0, gA0);            CP16(sA1, gA1);
    CP16(sB0, gB0);            CP16(sB1, gB1);
    CP_COMMIT();
    CP16(sA0 + ZQ_STAGE, gA0 + 64); CP16(sA1 + ZQ_STAGE, gA1 + 64);
    CP16(sB0 + ZQ_STAGE, gB0 + 64); CP16(sB1 + ZQ_STAGE, gB1 + 64);
    CP_COMMIT();

#pragma unroll 1
    for (int kc = 0; kc < 32; ++kc) {
        if (kc < 30) { CP_WAIT(1); } else { CP_WAIT(0); }
        __syncthreads();
        const char* sa = sm + (kc & 1) * ZQ_STAGE;
#pragma unroll
        for (int ks = 0; ks < 2; ++ks) {
            const int kb = (ks * 16 + 2 * tq) * 2;
            uint32_t ad[4][4];
#pragma unroll
            for (int mf = 0; mf < 4; ++mf) {
                int row = (wm * 64 + mf * 16 + g) * 80;
                ad[mf][0] = *(const uint32_t*)(sa + row + kb);
                ad[mf][1] = *(const uint32_t*)(sa + row + 640 + kb);
                ad[mf][2] = *(const uint32_t*)(sa + row + kb + 16);
                ad[mf][3] = *(const uint32_t*)(sa + row + 640 + kb + 16);
            }
#pragma unroll
            for (int nf = 0; nf < 4; ++nf) {
                int row = 10240 + (wn * 32 + nf * 8 + g) * 80;
                uint32_t b0 = *(const uint32_t*)(sa + row + kb);
                uint32_t b1 = *(const uint32_t*)(sa + row + kb + 16);
#pragma unroll
                for (int mf = 0; mf < 4; ++mf)
                    mma16816(acc[mf][nf], ad[mf], b0, b1);
            }
        }
        __syncthreads();
        if (kc + 2 < 32) {
            const int koff = (kc + 2) * 64;
            const uint32_t so = (uint32_t)((kc & 1) * ZQ_STAGE);
            CP16(sA0 + so, gA0 + koff); CP16(sA1 + so, gA1 + koff);
            CP16(sB0 + so, gB0 + koff); CP16(sB1 + so, gB1 + koff);
        }
        CP_COMMIT();
    }

    // ---- epilogue: per-warp transpose -> coalesced (c,t) stores + mean + vq ----
    // Fully static unroll: acc never runtime-indexed -> stays in registers.
    float* sfrag = (float*)sm + w * 576;       // 64x9 fp32 per warp (18.4KB total)
    float vq = 0.f;
    const int tbase = t0 + wm * 64;
    const size_t obase = (size_t)n * CD * TT;
#pragma unroll
    for (int nf = 0; nf < 4; ++nf) {
        __syncwarp();
#pragma unroll
        for (int mf = 0; mf < 4; ++mf) {
            int rr = mf * 16 + g;
            sfrag[rr * 9 + 2 * tq]           = acc[mf][nf][0];
            sfrag[rr * 9 + 2 * tq + 1]       = acc[mf][nf][1];
            sfrag[(rr + 8) * 9 + 2 * tq]     = acc[mf][nf][2];
            sfrag[(rr + 8) * 9 + 2 * tq + 1] = acc[mf][nf][3];
        }
        __syncwarp();
#pragma unroll
        for (int col = 0; col < 8; ++col) {
            int c = c0 + wn * 32 + nf * 8 + col;
            float cm = g_cmean[c];
#pragma unroll
            for (int i = 0; i < 2; ++i) {
                int row = i * 32 + lane;
                float z = sfrag[row * 9 + col] + cm;
                size_t o = obase + (size_t)c * TT + tbase + row;
                float xv = x[o];
                out[o] = z;
                float d = z - xv;
                vq = fmaf(d, d, vq);
            }
        }
    }
    // block reduce vq
#pragma unroll
    for (int o = 16; o; o >>= 1) vq += __shfl_down_sync(0xffffffffu, vq, o);
    __syncthreads();
    float* red = (float*)sm;
    if (lane == 0) red[w] = vq;
    __syncthreads();
    if (tid == 0) {
        float s = 0.f;
#pragma unroll
        for (int i = 0; i < 8; ++i) s += red[i];
        atomicAdd(&g_vq, (double)s);
    }
}

// ---------------- K6: scalars ----------------
__global__ void finalize_kernel(float* __restrict__ out)
{
    const int j = threadIdx.x;
    double aps = 0.0;
#pragma unroll
    for (int s = 0; s < 32; ++s) aps += (double)g_avgp[s * NB + j];
    float ap = (float)(aps * (1.0 / 65536.0));
    float t1 = ap * logf(ap + 1e-5f);
    float pr = (float)g_counts[j] * (1.f / 65536.f);
    float t2 = pr * logf(pr + 1e-7f);

    __shared__ double r1[1024];
    __shared__ double r2[1024];
    r1[j] = (double)t1;
    r2[j] = (double)t2;
    __syncthreads();
    for (int s = 512; s >= 1; s >>= 1) {
        if (j < s) { r1[j] += r1[j + s]; r2[j] += r2[j + s]; }
        __syncthreads();
    }
    if (j == 0) {
        float avg_entropy = -(float)r1[0];
        float sample_entropy = -(float)(g_ent * (1.0 / 65536.0));
        out[33554432] = sample_entropy;
        out[33554433] = avg_entropy;
        out[33554434] = sample_entropy - avg_entropy;
        out[33554435] = expf(-(float)r2[0]);
        out[33554436] = (float)(g_vq * (1.0 / 33554432.0));
    }
}

// ---------------- launch ----------------
extern "C" void kernel_launch(void* const* d_in, const int* in_sizes, int n_in,
                              void* d_out, int out_size)
{
    const float* x  = (const float*)d_in[0];
    const float* cb = (const float*)d_in[1];
    const float* Wq = (const float*)d_in[2];
    const float* Wk = (const float*)d_in[3];
    float* out = (float*)d_out;

    cudaFuncSetAttribute(zq_mma_kernel, cudaFuncAttributeMaxDynamicSharedMemorySize, ZQ_SMEM);

    init_kernel<<<256, 256>>>();
    kproj_kernel<<<dim3(8, 16), 256>>>(cb, Wk);
    ksumsq_kernel<<<128, 256>>>();
    knorm_kernel<<<2048, 256>>>();
    qproj_kernel<<<dim3(8, 1024), 256>>>(x, Wq);
    qnorm_kernel<<<8192, 256>>>();
    logits_kernel<<<dim3(16, 1024), 256>>>();
    cbt_kernel<<<2048, 256>>>(cb);
    colsum_kernel<<<2, 256>>>(cb);
    rowpass_kernel<<<8192, 256>>>(out);
    zq_mma_kernel<<<dim3(4, 512), 256, ZQ_SMEM>>>(x, out);
    finalize_kernel<<<1, 1024>>>(out);
}